// round 9
// baseline (speedup 1.0000x reference)
#include <cuda_runtime.h>

#define NN   91136
#define NEDGE 1000000
#define KK   3
#define TT   5
#define HID  32
#define EPSF 1e-5f
#define NGRAPH 32
#define NODES_PER_GRAPH 2848

// ---------------- scratch (device globals; no allocations allowed) ----------------
__device__ int   g_is64;
__device__ int   g_rowi[NEDGE];
__device__ int   g_coli[NEDGE];
__device__ float g_normv[NEDGE];
__device__ float g_deg[NN];
__device__ float g_dis[NN];
__device__ int   g_cnt[NN];
__device__ int   g_ptr[NN + 1];
__device__ int   g_cur[NN];
__device__ int2  g_edge[NEDGE];   // packed {src, weight-bits}
__device__ float g_H[NN * KK * HID];   // interleaved: [node][k][hid]
__device__ float g_R[KK * NN * HID];   // planar: [k][node][hid]
__device__ float g_OUT[KK * NN * HID];
__device__ float g_X[NN * HID];
__device__ float g_Y[NN * HID];
__device__ float g_H3[KK * NN];
__device__ float g_R3[KK * NN];
__device__ float g_OUT3[KK * NN];
__device__ float g_Y3[NN];
__device__ float g_logits[NN];
__device__ float g_stats[64];

__device__ __forceinline__ float wred(float v) {
#pragma unroll
    for (int o = 16; o; o >>= 1) v += __shfl_xor_sync(0xffffffffu, v, o);
    return v;
}

// ---------------- setup: dtype detect, convert, norm, CSR ----------------

__global__ void k_detect(const int* __restrict__ p) {
    __shared__ int nz;
    if (threadIdx.x == 0) nz = 0;
    __syncthreads();
    for (int i = threadIdx.x; i < 1024; i += blockDim.x)
        if (p[2 * i + 1] != 0) nz = 1;
    __syncthreads();
    if (threadIdx.x == 0) g_is64 = (nz == 0) ? 1 : 0;
}

__global__ void k_convert(const void* __restrict__ ei) {
    int e = blockIdx.x * blockDim.x + threadIdx.x;
    if (e >= NEDGE) return;
    if (g_is64) {
        const long long* p = (const long long*)ei;
        g_rowi[e] = (int)p[e];
        g_coli[e] = (int)p[NEDGE + e];
    } else {
        const int* p = (const int*)ei;
        g_rowi[e] = p[e];
        g_coli[e] = p[NEDGE + e];
    }
}

__global__ void k_zero_setup() {
    int i = blockIdx.x * blockDim.x + threadIdx.x;
    if (i < NN) { g_deg[i] = 0.f; g_cnt[i] = 0; }
}

__global__ void k_deg(const float* __restrict__ wts) {
    int e = blockIdx.x * blockDim.x + threadIdx.x;
    if (e >= NEDGE) return;
    int c = g_coli[e];
    atomicAdd(&g_deg[c], wts[e]);
    atomicAdd(&g_cnt[c], 1);
}

__global__ void k_dis() {
    int n = blockIdx.x * blockDim.x + threadIdx.x;
    if (n >= NN) return;
    float d = g_deg[n];
    g_dis[n] = (d > 0.f) ? rsqrtf(d) : 0.f;
}

__global__ void k_norm(const float* __restrict__ wts) {
    int e = blockIdx.x * blockDim.x + threadIdx.x;
    if (e >= NEDGE) return;
    g_normv[e] = g_dis[g_rowi[e]] * wts[e] * g_dis[g_coli[e]];
}

__global__ void k_scan() {
    __shared__ int sh[1024];
    __shared__ int s_off;
    int t = threadIdx.x;
    if (t == 0) s_off = 0;
    __syncthreads();
    for (int base = 0; base < NN; base += 1024) {
        int i = base + t;
        int v = (i < NN) ? g_cnt[i] : 0;
        sh[t] = v;
        __syncthreads();
#pragma unroll
        for (int d = 1; d < 1024; d <<= 1) {
            int add = (t >= d) ? sh[t - d] : 0;
            __syncthreads();
            sh[t] += add;
            __syncthreads();
        }
        int excl = s_off + sh[t] - v;
        if (i < NN) { g_ptr[i] = excl; g_cur[i] = excl; }
        int tot = sh[1023];
        __syncthreads();
        if (t == 0) s_off += tot;
        __syncthreads();
    }
    if (t == 0) g_ptr[NN] = s_off;
}

__global__ void k_scatter() {
    int e = blockIdx.x * blockDim.x + threadIdx.x;
    if (e >= NEDGE) return;
    int c = g_coli[e];
    int p = atomicAdd(&g_cur[c], 1);
    int2 rec;
    rec.x = g_rowi[e];
    rec.y = __float_as_int(g_normv[e]);
    g_edge[p] = rec;
}

// ---------------- dense kernels (H = in @ W, R = X @ rw + b), Fout = 32 ----------------
// warp per node, lane = output feature, k on gridDim.y, weight columns in registers.
// H written interleaved [n][k][hid]; R planar [k][n][hid].
template <int FH, int FX, bool PERK, bool XG>
__global__ __launch_bounds__(256) void k_dense32(
    const float* __restrict__ X,
    const float* __restrict__ wH,    // [K, FH, 32]
    const float* __restrict__ rw,    // [K, FX, 32]
    const float* __restrict__ bias)  // [K, 32]
{
    int k = blockIdx.y;
    int lane = threadIdx.x & 31;
    int warp = (blockIdx.x * blockDim.x + threadIdx.x) >> 5;
    int nwarps = (gridDim.x * blockDim.x) >> 5;

    float whc[FH], rwc[FX];
#pragma unroll
    for (int i = 0; i < FH; i++) whc[i] = wH[(k * FH + i) * HID + lane];
#pragma unroll
    for (int i = 0; i < FX; i++) rwc[i] = rw[(k * FX + i) * HID + lane];
    float bv = bias[k * HID + lane];

    for (int n = warp; n < NN; n += nwarps) {
        float xv = (lane < FX) ? (XG ? g_X[n * FX + lane] : X[n * FX + lane]) : 0.f;
        float hv;
        if (PERK) hv = g_OUT[(k * NN + n) * HID + lane];
        else      hv = (lane < FH) ? (XG ? g_X[n * FH + lane] : X[n * FH + lane]) : 0.f;

        float aH = 0.f, aR = bv;
#pragma unroll
        for (int i = 0; i < FH; i++) aH += __shfl_sync(0xffffffffu, hv, i) * whc[i];
#pragma unroll
        for (int i = 0; i < FX; i++) aR += __shfl_sync(0xffffffffu, xv, i) * rwc[i];

        g_H[(n * KK + k) * HID + lane] = aH;
        g_R[(k * NN + n) * HID + lane] = aR;
    }
}

// ---------------- SpMM (gather-only): OUT[k] = relu(S @ H[k] + R[k]) ----------------
template <bool LAST>
__global__ __launch_bounds__(256) void k_spmm32() {
    int lane = threadIdx.x & 31;
    int n = (blockIdx.x * blockDim.x + threadIdx.x) >> 5;
    if (n >= NN) return;
    int s0 = g_ptr[n], s1 = g_ptr[n + 1];
    float a0 = g_R[(0 * NN + n) * HID + lane];
    float a1 = g_R[(1 * NN + n) * HID + lane];
    float a2 = g_R[(2 * NN + n) * HID + lane];
#pragma unroll 4
    for (int e = s0; e < s1; e++) {
        int2 rec = g_edge[e];
        const float* hp = &g_H[rec.x * (KK * HID)];
        float w = __int_as_float(rec.y);
        a0 += w * hp[0 * HID + lane];
        a1 += w * hp[1 * HID + lane];
        a2 += w * hp[2 * HID + lane];
    }
    a0 = fmaxf(a0, 0.f); a1 = fmaxf(a1, 0.f); a2 = fmaxf(a2, 0.f);
    g_OUT[(0 * NN + n) * HID + lane] = a0;
    g_OUT[(1 * NN + n) * HID + lane] = a1;
    g_OUT[(2 * NN + n) * HID + lane] = a2;
    if (LAST) g_Y[n * HID + lane] = (a0 + a1 + a2) * (1.f / 3.f);
}

// ---------------- batch norm (32 features) ----------------
__global__ void k_zero_stats() {
    if (threadIdx.x < 64) g_stats[threadIdx.x] = 0.f;
}

__global__ void k_stats32() {
    int f = threadIdx.x & 31;
    int n0 = (blockIdx.x * blockDim.x + threadIdx.x) >> 5;
    int stride = (gridDim.x * blockDim.x) >> 5;
    float s = 0.f, q = 0.f;
    for (int n = n0; n < NN; n += stride) {
        float v = g_Y[n * HID + f];
        s += v; q += v * v;
    }
    __shared__ float ss[32], sq[32];
    if (threadIdx.x < 32) { ss[threadIdx.x] = 0.f; sq[threadIdx.x] = 0.f; }
    __syncthreads();
    atomicAdd(&ss[f], s);
    atomicAdd(&sq[f], q);
    __syncthreads();
    if (threadIdx.x < 32) {
        atomicAdd(&g_stats[threadIdx.x], ss[threadIdx.x]);
        atomicAdd(&g_stats[32 + threadIdx.x], sq[threadIdx.x]);
    }
}

__global__ void k_bn32(const float* __restrict__ g, const float* __restrict__ be) {
    int i = blockIdx.x * blockDim.x + threadIdx.x;
    if (i >= NN * HID) return;
    int f = i & 31;
    float m = g_stats[f] * (1.f / NN);
    float v = g_stats[32 + f] * (1.f / NN) - m * m;
    float y = fmaxf((g_Y[i] - m) * rsqrtf(v + EPSF) * g[f] + be[f], 0.f);
    g_X[i] = y;
}

// ---------------- layer 3 (Fout = 1) ----------------
template <bool T0>
__global__ __launch_bounds__(256) void k_dense3(
    const float* __restrict__ iw3,   // [K,32]
    const float* __restrict__ w3t,   // [K] (t>0)
    const float* __restrict__ rw3t,  // [K,32]
    const float* __restrict__ b3t)   // [K]
{
    int lane = threadIdx.x & 31;
    int n = (blockIdx.x * blockDim.x + threadIdx.x) >> 5;
    if (n >= NN) return;
    float xv = g_X[n * HID + lane];
#pragma unroll
    for (int k = 0; k < KK; k++) {
        float r = wred(xv * rw3t[k * HID + lane]) + b3t[k];
        float h;
        if (T0) h = wred(xv * iw3[k * HID + lane]);
        else    h = g_OUT3[k * NN + n] * w3t[k];
        if (lane == 0) {
            g_R3[k * NN + n] = r;
            g_H3[k * NN + n] = h;
        }
    }
}

template <bool LAST>
__global__ __launch_bounds__(256) void k_spmm3() {
    int lane = threadIdx.x & 31;
    int n = (blockIdx.x * blockDim.x + threadIdx.x) >> 5;
    if (n >= NN) return;
    int s0 = g_ptr[n], s1 = g_ptr[n + 1];
    float a0 = 0.f, a1 = 0.f, a2 = 0.f;
    for (int e = s0 + lane; e < s1; e += 32) {
        int2 rec = g_edge[e];
        int s = rec.x;
        float w = __int_as_float(rec.y);
        a0 += w * g_H3[0 * NN + s];
        a1 += w * g_H3[1 * NN + s];
        a2 += w * g_H3[2 * NN + s];
    }
    a0 = wred(a0); a1 = wred(a1); a2 = wred(a2);
    if (lane == 0) {
        float o0 = fmaxf(a0 + g_R3[0 * NN + n], 0.f);
        float o1 = fmaxf(a1 + g_R3[1 * NN + n], 0.f);
        float o2 = fmaxf(a2 + g_R3[2 * NN + n], 0.f);
        g_OUT3[0 * NN + n] = o0;
        g_OUT3[1 * NN + n] = o1;
        g_OUT3[2 * NN + n] = o2;
        if (LAST) g_Y3[n] = (o0 + o1 + o2) * (1.f / 3.f);
    }
}

__global__ void k_stats1() {
    int i = blockIdx.x * blockDim.x + threadIdx.x;
    int stride = gridDim.x * blockDim.x;
    float s = 0.f, q = 0.f;
    for (int n = i; n < NN; n += stride) {
        float v = g_Y3[n];
        s += v; q += v * v;
    }
    s = wred(s); q = wred(q);
    if ((threadIdx.x & 31) == 0) {
        atomicAdd(&g_stats[0], s);
        atomicAdd(&g_stats[1], q);
    }
}

// final BN + classifier; writes g_logits and (optionally) node logits straight to out
__global__ void k_final3(const float* __restrict__ g3, const float* __restrict__ be3,
                         const float* __restrict__ cw, const float* __restrict__ cb,
                         float* __restrict__ out, int write_out) {
    int n = blockIdx.x * blockDim.x + threadIdx.x;
    if (n >= NN) return;
    float m = g_stats[0] * (1.f / NN);
    float v = g_stats[1] * (1.f / NN) - m * m;
    float h = fmaxf((g_Y3[n] - m) * rsqrtf(v + EPSF) * g3[0] + be3[0], 0.f);
    float lg = h * cw[0] + cb[0];
    g_logits[n] = lg;
    if (write_out) out[n] = lg;
}

__global__ void k_gmax(float* __restrict__ out, int base) {
    __shared__ float sm[256];
    int b = blockIdx.x;
    int t = threadIdx.x;
    float m = -3.4e38f;
    for (int i = t; i < NODES_PER_GRAPH; i += 256)
        m = fmaxf(m, g_logits[b * NODES_PER_GRAPH + i]);
    sm[t] = m;
    __syncthreads();
    for (int s = 128; s; s >>= 1) {
        if (t < s) sm[t] = fmaxf(sm[t], sm[t + s]);
        __syncthreads();
    }
    if (t == 0) out[base + b] = sm[0];
}

// ---------------- launch ----------------
extern "C" void kernel_launch(void* const* d_in, const int* in_sizes, int n_in,
                              void* d_out, int out_size) {
    const float* x   = (const float*)d_in[0];
    const void*  ei  = d_in[1];
    const float* wts = (const float*)d_in[2];
    const float* iw1 = (const float*)d_in[4];
    const float* w1  = (const float*)d_in[5];
    const float* rw1 = (const float*)d_in[6];
    const float* b1  = (const float*)d_in[7];
    const float* gg1 = (const float*)d_in[8];
    const float* be1 = (const float*)d_in[9];
    const float* iw2 = (const float*)d_in[10];
    const float* w2  = (const float*)d_in[11];
    const float* rw2 = (const float*)d_in[12];
    const float* b2  = (const float*)d_in[13];
    const float* gg2 = (const float*)d_in[14];
    const float* be2 = (const float*)d_in[15];
    const float* iw3 = (const float*)d_in[16];
    const float* w3  = (const float*)d_in[17];
    const float* rw3 = (const float*)d_in[18];
    const float* b3  = (const float*)d_in[19];
    const float* gg3 = (const float*)d_in[20];
    const float* be3 = (const float*)d_in[21];
    const float* cw  = (const float*)d_in[22];
    const float* cb  = (const float*)d_in[23];
    float* out = (float*)d_out;

    const int TPB = 256;
    int gE  = (NEDGE + TPB - 1) / TPB;
    int gN  = (NN + TPB - 1) / TPB;
    int gNW = (NN * 32 + TPB - 1) / TPB;     // warp-per-node grids
    int gNF = (NN * HID + TPB - 1) / TPB;

    // setup: indices, norm, CSR
    k_detect<<<1, 256>>>((const int*)ei);
    k_convert<<<gE, TPB>>>(ei);
    k_zero_setup<<<gN, TPB>>>();
    k_deg<<<gE, TPB>>>(wts);
    k_dis<<<gN, TPB>>>();
    k_norm<<<gE, TPB>>>(wts);
    k_scan<<<1, 1024>>>();
    k_scatter<<<gE, TPB>>>();

    dim3 gd(592, 3);

    // ---- ARMA layer 1 (Fin=2 -> 32) ----
    for (int t = 0; t < TT; t++) {
        if (t == 0)
            k_dense32<2, 2, false, false><<<gd, TPB>>>(x, iw1, rw1 + t * KK * 2 * HID, b1 + t * KK * HID);
        else
            k_dense32<32, 2, true, false><<<gd, TPB>>>(x, w1 + (t - 1) * KK * HID * HID,
                                                       rw1 + t * KK * 2 * HID, b1 + t * KK * HID);
        if (t == TT - 1) k_spmm32<true><<<gNW, TPB>>>();
        else             k_spmm32<false><<<gNW, TPB>>>();
    }
    k_zero_stats<<<1, 64>>>();
    k_stats32<<<256, TPB>>>();
    k_bn32<<<gNF, TPB>>>(gg1, be1);

    // ---- ARMA layer 2 (32 -> 32) ----
    for (int t = 0; t < TT; t++) {
        if (t == 0)
            k_dense32<32, 32, false, true><<<gd, TPB>>>(x, iw2, rw2 + t * KK * HID * HID, b2 + t * KK * HID);
        else
            k_dense32<32, 32, true, true><<<gd, TPB>>>(x, w2 + (t - 1) * KK * HID * HID,
                                                       rw2 + t * KK * HID * HID, b2 + t * KK * HID);
        if (t == TT - 1) k_spmm32<true><<<gNW, TPB>>>();
        else             k_spmm32<false><<<gNW, TPB>>>();
    }
    k_zero_stats<<<1, 64>>>();
    k_stats32<<<256, TPB>>>();
    k_bn32<<<gNF, TPB>>>(gg2, be2);

    // ---- ARMA layer 3 (32 -> 1) ----
    for (int t = 0; t < TT; t++) {
        if (t == 0)
            k_dense3<true><<<gNW, TPB>>>(iw3, w3, rw3 + t * KK * HID, b3 + t * KK);
        else
            k_dense3<false><<<gNW, TPB>>>(iw3, w3 + (t - 1) * KK, rw3 + t * KK * HID, b3 + t * KK);
        if (t == TT - 1) k_spmm3<true><<<gNW, TPB>>>();
        else             k_spmm3<false><<<gNW, TPB>>>();
    }
    k_zero_stats<<<1, 64>>>();
    k_stats1<<<64, TPB>>>();
    int write_nodes = (out_size >= NN) ? 1 : 0;
    k_final3<<<gN, TPB>>>(gg3, be3, cw, cb, out, write_nodes);

    // outputs: [logits_nodes (N)] ++ [logits_graph (32)]
    if (out_size >= NN + 32) k_gmax<<<32, 256>>>(out, NN);
    else if (out_size == 32) k_gmax<<<32, 256>>>(out, 0);
}

// round 12
// speedup vs baseline: 1.1044x; 1.1044x over previous
#include <cuda_runtime.h>
#include <cuda_fp16.h>

#define NN   91136
#define NEDGE 1000000
#define KK   3
#define TT   5
#define HID  32
#define EPSF 1e-5f
#define NGRAPH 32
#define NODES_PER_GRAPH 2848
#define SCAN_BLOCKS 89          // 89 * 1024 == 91136 exactly

// ---------------- scratch (device globals; no allocations allowed) ----------------
__device__ int    g_is64;
__device__ int    g_rowi[NEDGE];
__device__ int    g_coli[NEDGE];
__device__ float  g_normv[NEDGE];
__device__ float  g_deg[NN];
__device__ float  g_dis[NN];
__device__ int    g_cnt[NN];
__device__ int    g_ptr[NN + 1];
__device__ int    g_cur[NN];
__device__ int    g_bsum[SCAN_BLOCKS];
__device__ int    g_boff[SCAN_BLOCKS];
__device__ int2   g_edge[NEDGE];        // packed {src, weight-bits}
__device__ __half g_Hh[NN * KK * HID];  // fp16 gather table, interleaved [node][k][hid]
__device__ float  g_R[KK * NN * HID];   // planar: [k][node][hid]
__device__ float  g_OUT[KK * NN * HID];
__device__ float  g_X[NN * HID];
__device__ float  g_Y[NN * HID];
__device__ float  g_H3[KK * NN];
__device__ float  g_R3[KK * NN];
__device__ float  g_OUT3[KK * NN];
__device__ float  g_Y3[NN];
__device__ float  g_logits[NN];
__device__ float  g_stats[64];

__device__ __forceinline__ float wred(float v) {
#pragma unroll
    for (int o = 16; o; o >>= 1) v += __shfl_xor_sync(0xffffffffu, v, o);
    return v;
}

// ---------------- setup: dtype detect, convert, norm, CSR ----------------

__global__ void k_detect(const int* __restrict__ p) {
    __shared__ int nz;
    if (threadIdx.x == 0) nz = 0;
    __syncthreads();
    for (int i = threadIdx.x; i < 1024; i += blockDim.x)
        if (p[2 * i + 1] != 0) nz = 1;
    __syncthreads();
    if (threadIdx.x == 0) g_is64 = (nz == 0) ? 1 : 0;
}

__global__ void k_convert(const void* __restrict__ ei) {
    int e = blockIdx.x * blockDim.x + threadIdx.x;
    if (e >= NEDGE) return;
    if (g_is64) {
        const long long* p = (const long long*)ei;
        g_rowi[e] = (int)p[e];
        g_coli[e] = (int)p[NEDGE + e];
    } else {
        const int* p = (const int*)ei;
        g_rowi[e] = p[e];
        g_coli[e] = p[NEDGE + e];
    }
}

__global__ void k_zero_setup() {
    int i = blockIdx.x * blockDim.x + threadIdx.x;
    if (i < NN) { g_deg[i] = 0.f; g_cnt[i] = 0; }
}

__global__ void k_deg(const float* __restrict__ wts) {
    int e = blockIdx.x * blockDim.x + threadIdx.x;
    if (e >= NEDGE) return;
    int c = g_coli[e];
    atomicAdd(&g_deg[c], wts[e]);
    atomicAdd(&g_cnt[c], 1);
}

__global__ void k_dis() {
    int n = blockIdx.x * blockDim.x + threadIdx.x;
    if (n >= NN) return;
    float d = g_deg[n];
    g_dis[n] = (d > 0.f) ? rsqrtf(d) : 0.f;
}

__global__ void k_norm(const float* __restrict__ wts) {
    int e = blockIdx.x * blockDim.x + threadIdx.x;
    if (e >= NEDGE) return;
    g_normv[e] = g_dis[g_rowi[e]] * wts[e] * g_dis[g_coli[e]];
}

// ---- hierarchical scan: per-block scan -> scan of block sums -> add-back ----
__global__ void k_scanA() {
    __shared__ int sh[1024];
    int b = blockIdx.x, t = threadIdx.x;
    int i = b * 1024 + t;
    int v = g_cnt[i];
    sh[t] = v;
    __syncthreads();
#pragma unroll
    for (int d = 1; d < 1024; d <<= 1) {
        int add = (t >= d) ? sh[t - d] : 0;
        __syncthreads();
        sh[t] += add;
        __syncthreads();
    }
    g_ptr[i] = sh[t] - v;          // block-local exclusive
    if (t == 1023) g_bsum[b] = sh[1023];
}

__global__ void k_scanB() {
    if (threadIdx.x == 0) {
        int acc = 0;
        for (int b = 0; b < SCAN_BLOCKS; b++) {
            g_boff[b] = acc;
            acc += g_bsum[b];
        }
        g_ptr[NN] = acc;           // == NEDGE
    }
}

__global__ void k_scanC() {
    int b = blockIdx.x, t = threadIdx.x;
    int i = b * 1024 + t;
    int p = g_ptr[i] + g_boff[b];
    g_ptr[i] = p;
    g_cur[i] = p;
}

__global__ void k_scatter() {
    int e = blockIdx.x * blockDim.x + threadIdx.x;
    if (e >= NEDGE) return;
    int c = g_coli[e];
    int p = atomicAdd(&g_cur[c], 1);
    int2 rec;
    rec.x = g_rowi[e];
    rec.y = __float_as_int(g_normv[e]);
    g_edge[p] = rec;
}

// ---------------- dense kernels (H = in @ W -> fp16, R = X @ rw + b), Fout = 32 ------
template <int FH, int FX, bool PERK, bool XG>
__global__ __launch_bounds__(256) void k_dense32(
    const float* __restrict__ X,
    const float* __restrict__ wH,    // [K, FH, 32]
    const float* __restrict__ rw,    // [K, FX, 32]
    const float* __restrict__ bias)  // [K, 32]
{
    int k = blockIdx.y;
    int lane = threadIdx.x & 31;
    int warp = (blockIdx.x * blockDim.x + threadIdx.x) >> 5;
    int nwarps = (gridDim.x * blockDim.x) >> 5;

    float whc[FH], rwc[FX];
#pragma unroll
    for (int i = 0; i < FH; i++) whc[i] = wH[(k * FH + i) * HID + lane];
#pragma unroll
    for (int i = 0; i < FX; i++) rwc[i] = rw[(k * FX + i) * HID + lane];
    float bv = bias[k * HID + lane];

    for (int n = warp; n < NN; n += nwarps) {
        float xv = (lane < FX) ? (XG ? g_X[n * FX + lane] : X[n * FX + lane]) : 0.f;
        float hv;
        if (PERK) hv = g_OUT[(k * NN + n) * HID + lane];
        else      hv = (lane < FH) ? (XG ? g_X[n * FH + lane] : X[n * FH + lane]) : 0.f;

        float aH = 0.f, aR = bv;
#pragma unroll
        for (int i = 0; i < FH; i++) aH += __shfl_sync(0xffffffffu, hv, i) * whc[i];
#pragma unroll
        for (int i = 0; i < FX; i++) aR += __shfl_sync(0xffffffffu, xv, i) * rwc[i];

        g_Hh[(n * KK + k) * HID + lane] = __float2half(aH);
        g_R[(k * NN + n) * HID + lane] = aR;
    }
}

// ---------------- SpMM (gather-only, fp16 table): OUT[k] = relu(S @ H[k] + R[k]) ----
template <bool LAST>
__global__ __launch_bounds__(256) void k_spmm32() {
    int lane = threadIdx.x & 31;
    int n = (blockIdx.x * blockDim.x + threadIdx.x) >> 5;
    if (n >= NN) return;
    int s0 = g_ptr[n], s1 = g_ptr[n + 1];
    float a0 = g_R[(0 * NN + n) * HID + lane];
    float a1 = g_R[(1 * NN + n) * HID + lane];
    float a2 = g_R[(2 * NN + n) * HID + lane];
#pragma unroll 4
    for (int e = s0; e < s1; e++) {
        int2 rec = g_edge[e];
        const __half* hp = &g_Hh[rec.x * (KK * HID)];
        float w = __int_as_float(rec.y);
        a0 += w * __half2float(hp[0 * HID + lane]);
        a1 += w * __half2float(hp[1 * HID + lane]);
        a2 += w * __half2float(hp[2 * HID + lane]);
    }
    a0 = fmaxf(a0, 0.f); a1 = fmaxf(a1, 0.f); a2 = fmaxf(a2, 0.f);
    g_OUT[(0 * NN + n) * HID + lane] = a0;
    g_OUT[(1 * NN + n) * HID + lane] = a1;
    g_OUT[(2 * NN + n) * HID + lane] = a2;
    if (LAST) g_Y[n * HID + lane] = (a0 + a1 + a2) * (1.f / 3.f);
}

// ---------------- batch norm (32 features) ----------------
__global__ void k_zero_stats() {
    if (threadIdx.x < 64) g_stats[threadIdx.x] = 0.f;
}

__global__ void k_stats32() {
    int f = threadIdx.x & 31;
    int n0 = (blockIdx.x * blockDim.x + threadIdx.x) >> 5;
    int stride = (gridDim.x * blockDim.x) >> 5;
    float s = 0.f, q = 0.f;
    for (int n = n0; n < NN; n += stride) {
        float v = g_Y[n * HID + f];
        s += v; q += v * v;
    }
    __shared__ float ss[32], sq[32];
    if (threadIdx.x < 32) { ss[threadIdx.x] = 0.f; sq[threadIdx.x] = 0.f; }
    __syncthreads();
    atomicAdd(&ss[f], s);
    atomicAdd(&sq[f], q);
    __syncthreads();
    if (threadIdx.x < 32) {
        atomicAdd(&g_stats[threadIdx.x], ss[threadIdx.x]);
        atomicAdd(&g_stats[32 + threadIdx.x], sq[threadIdx.x]);
    }
}

__global__ void k_bn32(const float* __restrict__ g, const float* __restrict__ be) {
    int i = blockIdx.x * blockDim.x + threadIdx.x;
    if (i >= NN * HID) return;
    int f = i & 31;
    float m = g_stats[f] * (1.f / NN);
    float v = g_stats[32 + f] * (1.f / NN) - m * m;
    float y = fmaxf((g_Y[i] - m) * rsqrtf(v + EPSF) * g[f] + be[f], 0.f);
    g_X[i] = y;
}

// ---------------- layer 3 (Fout = 1) ----------------
template <bool T0>
__global__ __launch_bounds__(256) void k_dense3(
    const float* __restrict__ iw3,   // [K,32]
    const float* __restrict__ w3t,   // [K] (t>0)
    const float* __restrict__ rw3t,  // [K,32]
    const float* __restrict__ b3t)   // [K]
{
    int lane = threadIdx.x & 31;
    int n = (blockIdx.x * blockDim.x + threadIdx.x) >> 5;
    if (n >= NN) return;
    float xv = g_X[n * HID + lane];
#pragma unroll
    for (int k = 0; k < KK; k++) {
        float r = wred(xv * rw3t[k * HID + lane]) + b3t[k];
        float h;
        if (T0) h = wred(xv * iw3[k * HID + lane]);
        else    h = g_OUT3[k * NN + n] * w3t[k];
        if (lane == 0) {
            g_R3[k * NN + n] = r;
            g_H3[k * NN + n] = h;
        }
    }
}

template <bool LAST>
__global__ __launch_bounds__(256) void k_spmm3() {
    int lane = threadIdx.x & 31;
    int n = (blockIdx.x * blockDim.x + threadIdx.x) >> 5;
    if (n >= NN) return;
    int s0 = g_ptr[n], s1 = g_ptr[n + 1];
    float a0 = 0.f, a1 = 0.f, a2 = 0.f;
    for (int e = s0 + lane; e < s1; e += 32) {
        int2 rec = g_edge[e];
        int s = rec.x;
        float w = __int_as_float(rec.y);
        a0 += w * g_H3[0 * NN + s];
        a1 += w * g_H3[1 * NN + s];
        a2 += w * g_H3[2 * NN + s];
    }
    a0 = wred(a0); a1 = wred(a1); a2 = wred(a2);
    if (lane == 0) {
        float o0 = fmaxf(a0 + g_R3[0 * NN + n], 0.f);
        float o1 = fmaxf(a1 + g_R3[1 * NN + n], 0.f);
        float o2 = fmaxf(a2 + g_R3[2 * NN + n], 0.f);
        g_OUT3[0 * NN + n] = o0;
        g_OUT3[1 * NN + n] = o1;
        g_OUT3[2 * NN + n] = o2;
        if (LAST) g_Y3[n] = (o0 + o1 + o2) * (1.f / 3.f);
    }
}

__global__ void k_stats1() {
    int i = blockIdx.x * blockDim.x + threadIdx.x;
    int stride = gridDim.x * blockDim.x;
    float s = 0.f, q = 0.f;
    for (int n = i; n < NN; n += stride) {
        float v = g_Y3[n];
        s += v; q += v * v;
    }
    s = wred(s); q = wred(q);
    if ((threadIdx.x & 31) == 0) {
        atomicAdd(&g_stats[0], s);
        atomicAdd(&g_stats[1], q);
    }
}

__global__ void k_final3(const float* __restrict__ g3, const float* __restrict__ be3,
                         const float* __restrict__ cw, const float* __restrict__ cb,
                         float* __restrict__ out, int write_out) {
    int n = blockIdx.x * blockDim.x + threadIdx.x;
    if (n >= NN) return;
    float m = g_stats[0] * (1.f / NN);
    float v = g_stats[1] * (1.f / NN) - m * m;
    float h = fmaxf((g_Y3[n] - m) * rsqrtf(v + EPSF) * g3[0] + be3[0], 0.f);
    float lg = h * cw[0] + cb[0];
    g_logits[n] = lg;
    if (write_out) out[n] = lg;
}

__global__ void k_gmax(float* __restrict__ out, int base) {
    __shared__ float sm[256];
    int b = blockIdx.x;
    int t = threadIdx.x;
    float m = -3.4e38f;
    for (int i = t; i < NODES_PER_GRAPH; i += 256)
        m = fmaxf(m, g_logits[b * NODES_PER_GRAPH + i]);
    sm[t] = m;
    __syncthreads();
    for (int s = 128; s; s >>= 1) {
        if (t < s) sm[t] = fmaxf(sm[t], sm[t + s]);
        __syncthreads();
    }
    if (t == 0) out[base + b] = sm[0];
}

// ---------------- launch ----------------
extern "C" void kernel_launch(void* const* d_in, const int* in_sizes, int n_in,
                              void* d_out, int out_size) {
    const float* x   = (const float*)d_in[0];
    const void*  ei  = d_in[1];
    const float* wts = (const float*)d_in[2];
    const float* iw1 = (const float*)d_in[4];
    const float* w1  = (const float*)d_in[5];
    const float* rw1 = (const float*)d_in[6];
    const float* b1  = (const float*)d_in[7];
    const float* gg1 = (const float*)d_in[8];
    const float* be1 = (const float*)d_in[9];
    const float* iw2 = (const float*)d_in[10];
    const float* w2  = (const float*)d_in[11];
    const float* rw2 = (const float*)d_in[12];
    const float* b2  = (const float*)d_in[13];
    const float* gg2 = (const float*)d_in[14];
    const float* be2 = (const float*)d_in[15];
    const float* iw3 = (const float*)d_in[16];
    const float* w3  = (const float*)d_in[17];
    const float* rw3 = (const float*)d_in[18];
    const float* b3  = (const float*)d_in[19];
    const float* gg3 = (const float*)d_in[20];
    const float* be3 = (const float*)d_in[21];
    const float* cw  = (const float*)d_in[22];
    const float* cb  = (const float*)d_in[23];
    float* out = (float*)d_out;

    const int TPB = 256;
    int gE  = (NEDGE + TPB - 1) / TPB;
    int gN  = (NN + TPB - 1) / TPB;
    int gNW = (NN * 32 + TPB - 1) / TPB;     // warp-per-node grids
    int gNF = (NN * HID + TPB - 1) / TPB;

    // setup: indices, norm, CSR (hierarchical scan)
    k_detect<<<1, 256>>>((const int*)ei);
    k_convert<<<gE, TPB>>>(ei);
    k_zero_setup<<<gN, TPB>>>();
    k_deg<<<gE, TPB>>>(wts);
    k_dis<<<gN, TPB>>>();
    k_norm<<<gE, TPB>>>(wts);
    k_scanA<<<SCAN_BLOCKS, 1024>>>();
    k_scanB<<<1, 32>>>();
    k_scanC<<<SCAN_BLOCKS, 1024>>>();
    k_scatter<<<gE, TPB>>>();

    dim3 gd(592, 3);

    // ---- ARMA layer 1 (Fin=2 -> 32) ----
    for (int t = 0; t < TT; t++) {
        if (t == 0)
            k_dense32<2, 2, false, false><<<gd, TPB>>>(x, iw1, rw1 + t * KK * 2 * HID, b1 + t * KK * HID);
        else
            k_dense32<32, 2, true, false><<<gd, TPB>>>(x, w1 + (t - 1) * KK * HID * HID,
                                                       rw1 + t * KK * 2 * HID, b1 + t * KK * HID);
        if (t == TT - 1) k_spmm32<true><<<gNW, TPB>>>();
        else             k_spmm32<false><<<gNW, TPB>>>();
    }
    k_zero_stats<<<1, 64>>>();
    k_stats32<<<256, TPB>>>();
    k_bn32<<<gNF, TPB>>>(gg1, be1);

    // ---- ARMA layer 2 (32 -> 32) ----
    for (int t = 0; t < TT; t++) {
        if (t == 0)
            k_dense32<32, 32, false, true><<<gd, TPB>>>(x, iw2, rw2 + t * KK * HID * HID, b2 + t * KK * HID);
        else
            k_dense32<32, 32, true, true><<<gd, TPB>>>(x, w2 + (t - 1) * KK * HID * HID,
                                                       rw2 + t * KK * HID * HID, b2 + t * KK * HID);
        if (t == TT - 1) k_spmm32<true><<<gNW, TPB>>>();
        else             k_spmm32<false><<<gNW, TPB>>>();
    }
    k_zero_stats<<<1, 64>>>();
    k_stats32<<<256, TPB>>>();
    k_bn32<<<gNF, TPB>>>(gg2, be2);

    // ---- ARMA layer 3 (32 -> 1) ----
    for (int t = 0; t < TT; t++) {
        if (t == 0)
            k_dense3<true><<<gNW, TPB>>>(iw3, w3, rw3 + t * KK * HID, b3 + t * KK);
        else
            k_dense3<false><<<gNW, TPB>>>(iw3, w3 + (t - 1) * KK, rw3 + t * KK * HID, b3 + t * KK);
        if (t == TT - 1) k_spmm3<true><<<gNW, TPB>>>();
        else             k_spmm3<false><<<gNW, TPB>>>();
    }
    k_zero_stats<<<1, 64>>>();
    k_stats1<<<64, TPB>>>();
    int write_nodes = (out_size >= NN) ? 1 : 0;
    k_final3<<<gN, TPB>>>(gg3, be3, cw, cb, out, write_nodes);

    // outputs: [logits_nodes (N)] ++ [logits_graph (32)]
    if (out_size >= NN + 32) k_gmax<<<32, 256>>>(out, NN);
    else if (out_size == 32) k_gmax<<<32, 256>>>(out, 0);
}